// round 11
// baseline (speedup 1.0000x reference)
#include <cuda_runtime.h>
#include <cuda_bf16.h>
#include <cstdint>

// SKA: spatially-varying 3x3 grouped conv.
// x: (B=8, C=64, H=128, W=128) f32
// w: (B=8, C_w=8, 9, H, W) f32
// out[b, g*8+cw, h, col] = sum_{i,j} x_pad[..., h+i-1, col+j-1] * w[b, cw, i*3+j, h, col]
//
// Persistent blocks (456 = 3/SM) grid-striding over 8192 (b,cw,h) tiles with a
// register double buffer. L2 residency shaping via createpolicy + cache_hint:
//   - x/w loads:  ld.global.nc.L2::cache_hint  with evict_last policy
//   - out stores: st.global.L2::cache_hint     with evict_last policy (NEW)
// Full working set x+w+out = 105 MB < 126 MB L2. With ALL streams pinned
// evict_last, output dirty lines stay resident across graph replays: rewrites
// hit in L2 and steady-state DRAM traffic collapses toward zero. Kernel then
// runs against L2 bandwidth + L1 wavefront floors (~9-10 us).

#define B_   8
#define C_   64
#define H_   128
#define W_   128
#define CW_  8
#define G_   8
#define HW_  (H_ * W_)
#define NTILES (B_ * CW_ * H_)   // 8192
#define GRID_  456               // ~3 blocks per SM

__device__ __forceinline__ float4 ldg_pol(const float* p, uint64_t pol) {
    float4 v;
    asm volatile("ld.global.nc.L2::cache_hint.v4.f32 {%0,%1,%2,%3}, [%4], %5;"
                 : "=f"(v.x), "=f"(v.y), "=f"(v.z), "=f"(v.w)
                 : "l"(p), "l"(pol));
    return v;
}

__device__ __forceinline__ void stg_pol(float* p, float4 v, uint64_t pol) {
    asm volatile("st.global.L2::cache_hint.v4.f32 [%0], {%1,%2,%3,%4}, %5;"
                 :: "l"(p), "f"(v.x), "f"(v.y), "f"(v.z), "f"(v.w), "l"(pol)
                 : "memory");
}

struct TileBuf {
    float4 v[2][3];   // x rows for the 2 groups this warp owns
    float4 wv[9];     // 9 per-pixel weights (shared by both groups)
};

__device__ __forceinline__ void load_tile(
    TileBuf& tb, int t, int lane, int q,
    const float* __restrict__ x, const float* __restrict__ w, uint64_t pol_el)
{
    int h  = t & 127;
    int cw = (t >> 7) & 7;
    int b  = t >> 10;
    int col0 = lane << 2;

    const bool top = (h > 0);
    const bool bot = (h < H_ - 1);
    const float4 z4 = make_float4(0.f, 0.f, 0.f, 0.f);

    const int c0 = q * CW_ + cw;
    const int c1 = (q + 4) * CW_ + cw;
    const float* xr0 = x + ((size_t)(b * C_ + c0)) * HW_ + h * W_ + col0;
    const float* xr1 = x + ((size_t)(b * C_ + c1)) * HW_ + h * W_ + col0;

    tb.v[0][1] = ldg_pol(xr0, pol_el);
    tb.v[1][1] = ldg_pol(xr1, pol_el);
    tb.v[0][0] = top ? ldg_pol(xr0 - W_, pol_el) : z4;
    tb.v[1][0] = top ? ldg_pol(xr1 - W_, pol_el) : z4;
    tb.v[0][2] = bot ? ldg_pol(xr0 + W_, pol_el) : z4;
    tb.v[1][2] = bot ? ldg_pol(xr1 + W_, pol_el) : z4;

    const float* wbase = w + ((size_t)(b * CW_ + cw) * 9) * HW_ + h * W_ + col0;
#pragma unroll
    for (int k = 0; k < 9; k++) {
        tb.wv[k] = ldg_pol(wbase + (size_t)k * HW_, pol_el);
    }
}

__device__ __forceinline__ void compute_store(
    const TileBuf& tb, int t, int lane, int q, float* __restrict__ out,
    uint64_t pol_st)
{
    int h  = t & 127;
    int cw = (t >> 7) & 7;
    int b  = t >> 10;
    int col0 = lane << 2;

    float* ob = out + (size_t)b * C_ * HW_ + h * W_ + col0;

#pragma unroll
    for (int p = 0; p < 2; p++) {
        float acc0 = 0.f, acc1 = 0.f, acc2 = 0.f, acc3 = 0.f;
#pragma unroll
        for (int di = 0; di < 3; di++) {
            float4 vd = tb.v[p][di];
            float L = __shfl_up_sync(0xffffffffu, vd.w, 1);
            float R = __shfl_down_sync(0xffffffffu, vd.x, 1);
            if (lane == 0)  L = 0.f;
            if (lane == 31) R = 0.f;

            float4 wl = tb.wv[di * 3 + 0];
            float4 wc = tb.wv[di * 3 + 1];
            float4 wr = tb.wv[di * 3 + 2];

            acc0 = fmaf(L,    wl.x, acc0);
            acc0 = fmaf(vd.x, wc.x, acc0);
            acc0 = fmaf(vd.y, wr.x, acc0);

            acc1 = fmaf(vd.x, wl.y, acc1);
            acc1 = fmaf(vd.y, wc.y, acc1);
            acc1 = fmaf(vd.z, wr.y, acc1);

            acc2 = fmaf(vd.y, wl.z, acc2);
            acc2 = fmaf(vd.z, wc.z, acc2);
            acc2 = fmaf(vd.w, wr.z, acc2);

            acc3 = fmaf(vd.z, wl.w, acc3);
            acc3 = fmaf(vd.w, wc.w, acc3);
            acc3 = fmaf(R,    wr.w, acc3);
        }

        int c = (q + p * 4) * CW_ + cw;
        float4 o;
        o.x = acc0; o.y = acc1; o.z = acc2; o.w = acc3;
        stg_pol(ob + (size_t)c * HW_, o, pol_st);
    }
}

__global__ void __launch_bounds__(128, 3) ska_kernel(
    const float* __restrict__ x,
    const float* __restrict__ w,
    float* __restrict__ out)
{
    const int tid    = threadIdx.x;
    const int lane   = tid & 31;
    const int q      = tid >> 5;
    const int stride = gridDim.x;

    uint64_t pol_el;
    asm volatile("createpolicy.fractional.L2::evict_last.b64 %0, 1.0;" : "=l"(pol_el));

    TileBuf A, B;

    int tA = blockIdx.x;            // < NTILES since grid <= NTILES
    load_tile(A, tA, lane, q, x, w, pol_el);

    for (;;) {
        int tB = tA + stride;
        if (tB < NTILES) load_tile(B, tB, lane, q, x, w, pol_el);
        compute_store(A, tA, lane, q, out, pol_el);
        if (tB >= NTILES) break;

        tA = tB + stride;
        if (tA < NTILES) load_tile(A, tA, lane, q, x, w, pol_el);
        compute_store(B, tB, lane, q, out, pol_el);
        if (tA >= NTILES) break;
    }
}

extern "C" void kernel_launch(void* const* d_in, const int* in_sizes, int n_in,
                              void* d_out, int out_size) {
    const float* x = (const float*)d_in[0];
    const float* w = (const float*)d_in[1];
    float* out = (float*)d_out;

    ska_kernel<<<GRID_, 128>>>(x, w, out);
}

// round 12
// speedup vs baseline: 1.3423x; 1.3423x over previous
#include <cuda_runtime.h>
#include <cuda_bf16.h>
#include <cstdint>

// SKA: spatially-varying 3x3 grouped conv.
// x: (B=8, C=64, H=128, W=128) f32
// w: (B=8, C_w=8, 9, H, W) f32
// out[b, g*8+cw, h, col] = sum_{i,j} x_pad[..., h+i-1, col+j-1] * w[b, cw, i*3+j, h, col]
//
// Warp-tile = (b, cw, h-pair): one warp computes ALL 8 groups x 2 output rows.
//  - x rows per group: 4 (h0-1..h0+2) shared by both output rows (was 6)
//  - 18 per-pixel weight float4s loaded ONCE per warp, reused by all 8 groups
//  -> ~40% fewer LDG wavefronts, ~24% less L2 read traffic than round 10.
// L2 policy (round-10 proven): loads evict_last (x+w=71MB stays L2-resident
// across graph replays), stores evict_first (write stream is eviction victim).
// Persistent grid (456 blocks = 3/SM), lane = 4-wide column chunk, horizontal
// halo via warp shuffle.

#define B_   8
#define C_   64
#define H_   128
#define W_   128
#define CW_  8
#define G_   8
#define HW_  (H_ * W_)
#define NPAIRS 64
#define NTILES (B_ * CW_ * NPAIRS)   // 4096 warp-tiles
#define GRID_  456                   // 3 blocks/SM; 1824 warps

__device__ __forceinline__ float4 ldg_pol(const float* p, uint64_t pol) {
    float4 v;
    asm volatile("ld.global.nc.L2::cache_hint.v4.f32 {%0,%1,%2,%3}, [%4], %5;"
                 : "=f"(v.x), "=f"(v.y), "=f"(v.z), "=f"(v.w)
                 : "l"(p), "l"(pol));
    return v;
}

__device__ __forceinline__ void stg_pol(float* p, float4 v, uint64_t pol) {
    asm volatile("st.global.L2::cache_hint.v4.f32 [%0], {%1,%2,%3,%4}, %5;"
                 :: "l"(p), "f"(v.x), "f"(v.y), "f"(v.z), "f"(v.w), "l"(pol)
                 : "memory");
}

// accumulate one x-row's 3-tap contribution into acc (4 output columns)
__device__ __forceinline__ void row_fma(
    float4 vd, float L, float R,
    float4 wl, float4 wc, float4 wr, float4& a)
{
    a.x = fmaf(L,    wl.x, a.x);
    a.x = fmaf(vd.x, wc.x, a.x);
    a.x = fmaf(vd.y, wr.x, a.x);

    a.y = fmaf(vd.x, wl.y, a.y);
    a.y = fmaf(vd.y, wc.y, a.y);
    a.y = fmaf(vd.z, wr.y, a.y);

    a.z = fmaf(vd.y, wl.z, a.z);
    a.z = fmaf(vd.z, wc.z, a.z);
    a.z = fmaf(vd.w, wr.z, a.z);

    a.w = fmaf(vd.z, wl.w, a.w);
    a.w = fmaf(vd.w, wc.w, a.w);
    a.w = fmaf(R,    wr.w, a.w);
}

__global__ void __launch_bounds__(128, 3) ska_kernel(
    const float* __restrict__ x,
    const float* __restrict__ w,
    float* __restrict__ out)
{
    const int tid  = threadIdx.x;
    const int lane = tid & 31;
    const int q    = tid >> 5;
    const int col0 = lane << 2;
    const int wstride = GRID_ * 4;

    uint64_t pol_el, pol_ef;
    asm volatile("createpolicy.fractional.L2::evict_last.b64 %0, 1.0;"  : "=l"(pol_el));
    asm volatile("createpolicy.fractional.L2::evict_first.b64 %0, 1.0;" : "=l"(pol_ef));

    const float4 z4 = make_float4(0.f, 0.f, 0.f, 0.f);

    for (int t = blockIdx.x * 4 + q; t < NTILES; t += wstride) {
        int hp = t & 63;
        int cw = (t >> 6) & 7;
        int b  = t >> 9;
        int h0 = hp << 1;              // output rows h0, h0+1

        const bool top = (h0 > 0);
        const bool bot = (h0 < H_ - 2);

        // ---- 18 per-pixel weights: 9 for row h0, 9 for row h0+1 ----
        const float* wb = w + ((size_t)(b * CW_ + cw) * 9) * HW_ + h0 * W_ + col0;
        float4 wv0[9], wv1[9];
#pragma unroll
        for (int k = 0; k < 9; k++) {
            wv0[k] = ldg_pol(wb + (size_t)k * HW_,       pol_el);
            wv1[k] = ldg_pol(wb + (size_t)k * HW_ + W_,  pol_el);
        }

        const float* xb = x + (size_t)b * C_ * HW_ + h0 * W_ + col0;
        float* ob = out + (size_t)b * C_ * HW_ + h0 * W_ + col0;

        // ---- groups in batches of 2 (8 independent loads per batch) ----
#pragma unroll
        for (int gg = 0; gg < G_; gg += 2) {
            float4 v[2][4];   // rows h0-1, h0, h0+1, h0+2
#pragma unroll
            for (int p = 0; p < 2; p++) {
                int c = (gg + p) * CW_ + cw;
                const float* xr = xb + (size_t)c * HW_;
                v[p][0] = top ? ldg_pol(xr - W_,      pol_el) : z4;
                v[p][1] =       ldg_pol(xr,           pol_el);
                v[p][2] =       ldg_pol(xr + W_,      pol_el);
                v[p][3] = bot ? ldg_pol(xr + 2 * W_,  pol_el) : z4;
            }

#pragma unroll
            for (int p = 0; p < 2; p++) {
                // halo per row, computed once, shared by both output rows
                float L[4], R[4];
#pragma unroll
                for (int r = 0; r < 4; r++) {
                    L[r] = __shfl_up_sync(0xffffffffu, v[p][r].w, 1);
                    R[r] = __shfl_down_sync(0xffffffffu, v[p][r].x, 1);
                    if (lane == 0)  L[r] = 0.f;
                    if (lane == 31) R[r] = 0.f;
                }

                float4 a0 = z4, a1 = z4;
                // output row h0:   rows 0,1,2 with wv0
                row_fma(v[p][0], L[0], R[0], wv0[0], wv0[1], wv0[2], a0);
                row_fma(v[p][1], L[1], R[1], wv0[3], wv0[4], wv0[5], a0);
                row_fma(v[p][2], L[2], R[2], wv0[6], wv0[7], wv0[8], a0);
                // output row h0+1: rows 1,2,3 with wv1
                row_fma(v[p][1], L[1], R[1], wv1[0], wv1[1], wv1[2], a1);
                row_fma(v[p][2], L[2], R[2], wv1[3], wv1[4], wv1[5], a1);
                row_fma(v[p][3], L[3], R[3], wv1[6], wv1[7], wv1[8], a1);

                int c = (gg + p) * CW_ + cw;
                float* op = ob + (size_t)c * HW_;
                stg_pol(op,      a0, pol_ef);
                stg_pol(op + W_, a1, pol_ef);
            }
        }
    }
}

extern "C" void kernel_launch(void* const* d_in, const int* in_sizes, int n_in,
                              void* d_out, int out_size) {
    const float* x = (const float*)d_in[0];
    const float* w = (const float*)d_in[1];
    float* out = (float*)d_out;

    ska_kernel<<<GRID_, 128>>>(x, w, out);
}